// round 1
// baseline (speedup 1.0000x reference)
#include <cuda_runtime.h>
#include <math.h>

#define BB 4
#define SEQ 1024
#define DIMM 1024
#define NH 16
#define DHD 64
#define NMEM 16
#define JTOT (SEQ + NMEM)   /* 1040 */
#define ROWS (BB * SEQ)     /* 4096 */
#define QKSCALE 10.0f

// ------------------------- device scratch (no allocs) -------------------------
__device__ float g_qraw[ROWS * DIMM];
__device__ float g_kraw[ROWS * DIMM];
__device__ float g_vraw[ROWS * DIMM];
__device__ float g_vgate[ROWS * DIMM];
__device__ float g_hgate[ROWS * NH];
__device__ float g_q[(size_t)BB * NH * SEQ * DHD];
__device__ float g_k[(size_t)BB * NH * JTOT * DHD];
__device__ float g_v[(size_t)BB * NH * JTOT * DHD];
__device__ float g_dots[(size_t)BB * NH * SEQ * JTOT];  // 273 MB scratch, reused for attn
__device__ float g_outg[ROWS * DIMM];

// ---------------- SGEMM: C[M,N] = A[M,K] @ B[K,N], row-major -----------------
// 128x128 block tile, 8x8 per thread, BK=8. Assumes M%128==0 and K%8==0
// (true for all uses here); N guarded (handles N=16 for the head gate).
__global__ __launch_bounds__(256) void sgemm_k(const float* __restrict__ A,
                                               const float* __restrict__ Bm,
                                               float* __restrict__ C,
                                               int Mn, int Nn, int Kn) {
    __shared__ float As[8][128];
    __shared__ float Bs[8][128];
    int tid = threadIdx.x;
    int row0 = blockIdx.y * 128;
    int col0 = blockIdx.x * 128;
    int ty = tid >> 4, tx = tid & 15;
    float acc[8][8];
#pragma unroll
    for (int i = 0; i < 8; i++)
#pragma unroll
        for (int j = 0; j < 8; j++) acc[i][j] = 0.f;

    int arow = tid >> 1;
    int acol = (tid & 1) * 4;
    int brow = tid >> 5;
    int bcol = (tid & 31) * 4;

    for (int k0 = 0; k0 < Kn; k0 += 8) {
        float4 av = *reinterpret_cast<const float4*>(&A[(size_t)(row0 + arow) * Kn + k0 + acol]);
        As[acol + 0][arow] = av.x;
        As[acol + 1][arow] = av.y;
        As[acol + 2][arow] = av.z;
        As[acol + 3][arow] = av.w;
        if (col0 + bcol + 3 < Nn) {
            *reinterpret_cast<float4*>(&Bs[brow][bcol]) =
                *reinterpret_cast<const float4*>(&Bm[(size_t)(k0 + brow) * Nn + col0 + bcol]);
        } else {
#pragma unroll
            for (int u = 0; u < 4; u++)
                Bs[brow][bcol + u] =
                    (col0 + bcol + u < Nn) ? Bm[(size_t)(k0 + brow) * Nn + col0 + bcol + u] : 0.f;
        }
        __syncthreads();
#pragma unroll
        for (int k = 0; k < 8; k++) {
            float4 a0 = *reinterpret_cast<const float4*>(&As[k][ty * 8]);
            float4 a1 = *reinterpret_cast<const float4*>(&As[k][ty * 8 + 4]);
            float4 b0 = *reinterpret_cast<const float4*>(&Bs[k][tx * 8]);
            float4 b1 = *reinterpret_cast<const float4*>(&Bs[k][tx * 8 + 4]);
            float a[8] = {a0.x, a0.y, a0.z, a0.w, a1.x, a1.y, a1.z, a1.w};
            float b[8] = {b0.x, b0.y, b0.z, b0.w, b1.x, b1.y, b1.z, b1.w};
#pragma unroll
            for (int i = 0; i < 8; i++)
#pragma unroll
                for (int j = 0; j < 8; j++) acc[i][j] += a[i] * b[j];
        }
        __syncthreads();
    }
#pragma unroll
    for (int i = 0; i < 8; i++) {
        int r = row0 + ty * 8 + i;
#pragma unroll
        for (int j = 0; j < 8; j++) {
            int c = col0 + tx * 8 + j;
            if (c < Nn) C[(size_t)r * Nn + c] = acc[i][j];
        }
    }
}

// ------------- l2norm + per-dim scale + RoPE for q,k; transpose v -------------
// one warp per (b,n,h); lane handles interleaved pair (2*lane, 2*lane+1)
__global__ __launch_bounds__(256) void normrope_k(const float* __restrict__ freqs,
                                                  const float* __restrict__ q_scale,
                                                  const float* __restrict__ k_scale) {
    int gw = (blockIdx.x * blockDim.x + threadIdx.x) >> 5;
    int lane = threadIdx.x & 31;
    int row = gw / NH, h = gw - row * NH;
    int b = row / SEQ, n = row - b * SEQ;
    int d0 = lane * 2;
    size_t src = (size_t)row * DIMM + h * DHD + d0;
    float f = freqs[n * DHD + d0];
    float sf, cf;
    sincosf(f, &sf, &cf);
    {   // q
        float x0 = g_qraw[src], x1 = g_qraw[src + 1];
        float ss = x0 * x0 + x1 * x1;
#pragma unroll
        for (int o = 16; o; o >>= 1) ss += __shfl_xor_sync(0xffffffffu, ss, o);
        float inv = 1.f / fmaxf(sqrtf(ss), 1e-12f);
        x0 = x0 * inv * q_scale[h * DHD + d0];
        x1 = x1 * inv * q_scale[h * DHD + d0 + 1];
        size_t dst = ((size_t)(b * NH + h) * SEQ + n) * DHD + d0;
        g_q[dst] = x0 * cf - x1 * sf;
        g_q[dst + 1] = x1 * cf + x0 * sf;
    }
    {   // k (written after the NMEM memory slots)
        float x0 = g_kraw[src], x1 = g_kraw[src + 1];
        float ss = x0 * x0 + x1 * x1;
#pragma unroll
        for (int o = 16; o; o >>= 1) ss += __shfl_xor_sync(0xffffffffu, ss, o);
        float inv = 1.f / fmaxf(sqrtf(ss), 1e-12f);
        x0 = x0 * inv * k_scale[h * DHD + d0];
        x1 = x1 * inv * k_scale[h * DHD + d0 + 1];
        size_t dst = ((size_t)(b * NH + h) * JTOT + NMEM + n) * DHD + d0;
        g_k[dst] = x0 * cf - x1 * sf;
        g_k[dst + 1] = x1 * cf + x0 * sf;
    }
    {   // v transpose copy
        size_t dst = ((size_t)(b * NH + h) * JTOT + NMEM + n) * DHD + d0;
        g_v[dst] = g_vraw[src];
        g_v[dst + 1] = g_vraw[src + 1];
    }
}

// ------------- memory kv slots: l2norm(mem_k)*k_scale, copy mem_v -------------
__global__ __launch_bounds__(256) void memprep_k(const float* __restrict__ mem_k,
                                                 const float* __restrict__ mem_v,
                                                 const float* __restrict__ k_scale) {
    int gw = (blockIdx.x * blockDim.x + threadIdx.x) >> 5;  // [0, NH*NMEM)
    int lane = threadIdx.x & 31;
    int h = gw / NMEM, m = gw - h * NMEM;
    int d0 = lane * 2;
    float x0 = mem_k[(h * NMEM + m) * DHD + d0];
    float x1 = mem_k[(h * NMEM + m) * DHD + d0 + 1];
    float ss = x0 * x0 + x1 * x1;
#pragma unroll
    for (int o = 16; o; o >>= 1) ss += __shfl_xor_sync(0xffffffffu, ss, o);
    float inv = 1.f / fmaxf(sqrtf(ss), 1e-12f);
    x0 = x0 * inv * k_scale[h * DHD + d0];
    x1 = x1 * inv * k_scale[h * DHD + d0 + 1];
    float v0 = mem_v[(h * NMEM + m) * DHD + d0];
    float v1 = mem_v[(h * NMEM + m) * DHD + d0 + 1];
    for (int b = 0; b < BB; b++) {
        size_t dst = ((size_t)(b * NH + h) * JTOT + m) * DHD + d0;
        g_k[dst] = x0;
        g_k[dst + 1] = x1;
        g_v[dst] = v0;
        g_v[dst + 1] = v1;
    }
}

// ---------------- dots[b,h,i,j] = QKSCALE * q[b,h,i,:].k[b,h,j,:] -------------
__global__ __launch_bounds__(256) void dots_k() {
    __shared__ float Qs[64][68];  // [i][d], pitch 68 keeps float4 alignment
    __shared__ float Ks[64][68];  // transposed: [d][j]
    int bh = blockIdx.z;
    int i0 = blockIdx.y * 64;
    int j0 = blockIdx.x * 64;
    const float* Q = g_q + (size_t)bh * SEQ * DHD;
    const float* K = g_k + (size_t)bh * JTOT * DHD;
    int tid = threadIdx.x;
#pragma unroll
    for (int r = 0; r < 4; r++) {
        int l = tid + r * 256;
        int i = l >> 4;
        int d4 = (l & 15) * 4;
        float4 qv = *reinterpret_cast<const float4*>(&Q[(size_t)(i0 + i) * DHD + d4]);
        *reinterpret_cast<float4*>(&Qs[i][d4]) = qv;
    }
#pragma unroll
    for (int r = 0; r < 4; r++) {
        int l = tid + r * 256;
        int j = l >> 4;
        int d4 = (l & 15) * 4;
        int jj = j0 + j;
        float4 kv = make_float4(0.f, 0.f, 0.f, 0.f);
        if (jj < JTOT) kv = *reinterpret_cast<const float4*>(&K[(size_t)jj * DHD + d4]);
        Ks[d4 + 0][j] = kv.x;
        Ks[d4 + 1][j] = kv.y;
        Ks[d4 + 2][j] = kv.z;
        Ks[d4 + 3][j] = kv.w;
    }
    __syncthreads();
    int ty = tid >> 4, tx = tid & 15;
    float acc[4][4] = {};
#pragma unroll
    for (int d = 0; d < 64; d++) {
        float a[4];
#pragma unroll
        for (int ii = 0; ii < 4; ii++) a[ii] = Qs[ty * 4 + ii][d];
        float4 bv = *reinterpret_cast<const float4*>(&Ks[d][tx * 4]);
        float bb[4] = {bv.x, bv.y, bv.z, bv.w};
#pragma unroll
        for (int ii = 0; ii < 4; ii++)
#pragma unroll
            for (int jj = 0; jj < 4; jj++) acc[ii][jj] += a[ii] * bb[jj];
    }
    float* D = g_dots + (size_t)bh * SEQ * JTOT;
#pragma unroll
    for (int ii = 0; ii < 4; ii++) {
        int i = i0 + ty * 4 + ii;
#pragma unroll
        for (int jj = 0; jj < 4; jj++) {
            int j = j0 + tx * 4 + jj;
            if (j < JTOT) D[(size_t)i * JTOT + j] = acc[ii][jj] * QKSCALE;
        }
    }
}

// ------- pre-mix (talking heads) + causal mask + softmax + post-mix, in place -
// one block per (b, i): needs all 16 heads' score rows simultaneously.
__global__ __launch_bounds__(256) void mixsoft_k(const float* __restrict__ W_pre,
                                                 const float* __restrict__ W_post) {
    extern __shared__ float sm[];
    float* S = sm;               // NH * JTOT raw scores
    float* Mx = sm + NH * JTOT;  // NH * JTOT mixed / probs
    __shared__ float wpre[NH * NH], wpost[NH * NH], inv_l[NH];
    int i = blockIdx.x, b = blockIdx.y;
    int tid = threadIdx.x;
    wpre[tid] = W_pre[tid];    // 256 == NH*NH
    wpost[tid] = W_post[tid];
    size_t base = ((size_t)(b * NH) * SEQ + i) * JTOT;
    for (int h = 0; h < NH; h++) {
        size_t off = base + (size_t)h * SEQ * JTOT;
        for (int j = tid; j < JTOT; j += 256) S[h * JTOT + j] = g_dots[off + j];
    }
    __syncthreads();
    int jlim = i + NMEM;  // valid: j <= i + (JTOT - SEQ)
    for (int j = tid; j < JTOT; j += 256) {
        float sv[NH];
#pragma unroll
        for (int h = 0; h < NH; h++) sv[h] = S[h * JTOT + j];
        bool masked = j > jlim;
#pragma unroll
        for (int g = 0; g < NH; g++) {
            float a = 0.f;
#pragma unroll
            for (int h = 0; h < NH; h++) a += wpre[g * NH + h] * sv[h];
            Mx[g * JTOT + j] = masked ? -3.0e38f : a;
        }
    }
    __syncthreads();
    int w = tid >> 5, lane = tid & 31;
    for (int g = w; g < NH; g += 8) {
        float mx = -3.0e38f;
        for (int j = lane; j < JTOT; j += 32) mx = fmaxf(mx, Mx[g * JTOT + j]);
#pragma unroll
        for (int o = 16; o; o >>= 1) mx = fmaxf(mx, __shfl_xor_sync(0xffffffffu, mx, o));
        float sum = 0.f;
        for (int j = lane; j < JTOT; j += 32) {
            float e = __expf(Mx[g * JTOT + j] - mx);
            Mx[g * JTOT + j] = e;
            sum += e;
        }
#pragma unroll
        for (int o = 16; o; o >>= 1) sum += __shfl_xor_sync(0xffffffffu, sum, o);
        if (lane == 0) inv_l[g] = 1.f / sum;
    }
    __syncthreads();
    for (int j = tid; j < JTOT; j += 256) {
        float pv[NH];
#pragma unroll
        for (int h = 0; h < NH; h++) pv[h] = Mx[h * JTOT + j] * inv_l[h];
#pragma unroll
        for (int g = 0; g < NH; g++) {
            float a = 0.f;
#pragma unroll
            for (int h = 0; h < NH; h++) a += wpost[g * NH + h] * pv[h];
            g_dots[base + (size_t)g * SEQ * JTOT + j] = a;
        }
    }
}

// ------------ out[b,g,i,d] = sum_j attn * v, fused head/value gates -----------
__global__ __launch_bounds__(256) void outgemm_k(const float* __restrict__ b_h,
                                                 const float* __restrict__ b_v,
                                                 float* __restrict__ outg) {
    __shared__ float As[16][68];  // [k][i]
    __shared__ float Vs[16][68];  // [k][d]
    int bg = blockIdx.y;
    int b = bg >> 4, g = bg & 15;
    int i0 = blockIdx.x * 64;
    const float* Arow = g_dots + (size_t)bg * SEQ * JTOT;
    const float* V = g_v + (size_t)bg * JTOT * DHD;
    int tid = threadIdx.x;
    int ty = tid >> 4, tx = tid & 15;
    float acc[4][4] = {};
    for (int k0 = 0; k0 < JTOT; k0 += 16) {
        {
            int i = tid >> 2;
            int c4 = (tid & 3) * 4;
            float4 av = *reinterpret_cast<const float4*>(&Arow[(size_t)(i0 + i) * JTOT + k0 + c4]);
            As[c4 + 0][i] = av.x;
            As[c4 + 1][i] = av.y;
            As[c4 + 2][i] = av.z;
            As[c4 + 3][i] = av.w;
        }
        {
            int kk = tid >> 4;
            int d4 = (tid & 15) * 4;
            *reinterpret_cast<float4*>(&Vs[kk][d4]) =
                *reinterpret_cast<const float4*>(&V[(size_t)(k0 + kk) * DHD + d4]);
        }
        __syncthreads();
#pragma unroll
        for (int kk = 0; kk < 16; kk++) {
            float a[4];
#pragma unroll
            for (int ii = 0; ii < 4; ii++) a[ii] = As[kk][ty * 4 + ii];
            float4 vv = *reinterpret_cast<const float4*>(&Vs[kk][tx * 4]);
            float vb[4] = {vv.x, vv.y, vv.z, vv.w};
#pragma unroll
            for (int ii = 0; ii < 4; ii++)
#pragma unroll
                for (int jj = 0; jj < 4; jj++) acc[ii][jj] += a[ii] * vb[jj];
        }
        __syncthreads();
    }
#pragma unroll
    for (int ii = 0; ii < 4; ii++) {
        int i = i0 + ty * 4 + ii;
        int r = b * SEQ + i;
        float hg = 1.f / (1.f + __expf(-(g_hgate[r * NH + g] + b_h[g])));
#pragma unroll
        for (int jj = 0; jj < 4; jj++) {
            int d = tx * 4 + jj;
            int c = g * DHD + d;
            float vg = 1.f / (1.f + __expf(-(g_vgate[(size_t)r * DIMM + c] + b_v[c])));
            outg[(size_t)r * DIMM + c] = acc[ii][jj] * hg * vg;
        }
    }
}

// ------------------------------------------------------------------------------
extern "C" void kernel_launch(void* const* d_in, const int* in_sizes, int n_in,
                              void* d_out, int out_size) {
    const float* x       = (const float*)d_in[0];
    const float* freqs   = (const float*)d_in[1];
    const float* Wq      = (const float*)d_in[2];
    const float* Wk      = (const float*)d_in[3];
    const float* Wv      = (const float*)d_in[4];
    const float* q_scale = (const float*)d_in[5];
    const float* k_scale = (const float*)d_in[6];
    const float* mem_k   = (const float*)d_in[7];
    const float* mem_v   = (const float*)d_in[8];
    const float* W_pre   = (const float*)d_in[9];
    const float* W_post  = (const float*)d_in[10];
    const float* W_hgate = (const float*)d_in[11];
    const float* b_hgate = (const float*)d_in[12];
    const float* W_vgate = (const float*)d_in[13];
    const float* b_vgate = (const float*)d_in[14];
    const float* Wo      = (const float*)d_in[15];
    float* out = (float*)d_out;

    float *qraw, *kraw, *vraw, *vgate, *hgate, *outg;
    cudaGetSymbolAddress((void**)&qraw, g_qraw);
    cudaGetSymbolAddress((void**)&kraw, g_kraw);
    cudaGetSymbolAddress((void**)&vraw, g_vraw);
    cudaGetSymbolAddress((void**)&vgate, g_vgate);
    cudaGetSymbolAddress((void**)&hgate, g_hgate);
    cudaGetSymbolAddress((void**)&outg, g_outg);

    dim3 gBig(DIMM / 128, ROWS / 128);  // (8, 32)

    // 1) projections + gate logits
    sgemm_k<<<gBig, 256>>>(x, Wq, qraw, ROWS, DIMM, DIMM);
    sgemm_k<<<gBig, 256>>>(x, Wk, kraw, ROWS, DIMM, DIMM);
    sgemm_k<<<gBig, 256>>>(x, Wv, vraw, ROWS, DIMM, DIMM);
    sgemm_k<<<gBig, 256>>>(x, W_vgate, vgate, ROWS, DIMM, DIMM);
    sgemm_k<<<dim3(1, ROWS / 128), 256>>>(x, W_hgate, hgate, ROWS, NH, DIMM);

    // 2) l2norm + scale + rope + head-major layout; memory kv slots
    normrope_k<<<(ROWS * NH) / 8, 256>>>(freqs, q_scale, k_scale);
    memprep_k<<<(NH * NMEM) / 8, 256>>>(mem_k, mem_v, k_scale);

    // 3) attention scores
    dots_k<<<dim3((JTOT + 63) / 64, SEQ / 64, BB * NH), 256>>>();

    // 4) talking-heads mix + causal softmax + post-mix (in place in g_dots)
    int smem = 2 * NH * JTOT * (int)sizeof(float);  // 133,120 B
    cudaFuncSetAttribute(mixsoft_k, cudaFuncAttributeMaxDynamicSharedMemorySize, smem);
    mixsoft_k<<<dim3(SEQ, BB), 256, smem>>>(W_pre, W_post);

    // 5) attn @ v + head gate + value gate
    outgemm_k<<<dim3(SEQ / 64, BB * NH), 256>>>(b_hgate, b_vgate, outg);

    // 6) output projection
    sgemm_k<<<gBig, 256>>>(outg, Wo, out, ROWS, DIMM, DIMM);
}

// round 2
// speedup vs baseline: 2.0400x; 2.0400x over previous
#include <cuda_runtime.h>
#include <math.h>

#define BB 4
#define SEQ 1024
#define DIMM 1024
#define NH 16
#define DHD 64
#define NMEM 16
#define JTOT (SEQ + NMEM)   /* 1040 */
#define ROWS (BB * SEQ)     /* 4096 */
#define QKSCALE 10.0f

// ------------------------- device scratch (no allocs) -------------------------
__device__ float g_qraw[ROWS * DIMM];
__device__ float g_kraw[ROWS * DIMM];
__device__ float g_vraw[ROWS * DIMM];
__device__ float g_vgate[ROWS * DIMM];
__device__ float g_hgate[ROWS * NH];
__device__ float g_q[(size_t)BB * NH * SEQ * DHD];
__device__ float g_k[(size_t)BB * NH * JTOT * DHD];
__device__ float g_v[(size_t)BB * NH * JTOT * DHD];
__device__ float g_dots[(size_t)BB * NH * SEQ * JTOT];  // 273 MB scratch, reused for attn
__device__ float g_outg[ROWS * DIMM];

// ------------------------------ tf32 helpers ---------------------------------
__device__ __forceinline__ unsigned tf32b(float x) {
    unsigned u;
    asm("cvt.rna.tf32.f32 %0, %1;" : "=r"(u) : "f"(x));
    return u;
}
__device__ __forceinline__ void mma_tf32(float c[4], const unsigned a[4], const unsigned b[2]) {
    asm volatile(
        "mma.sync.aligned.m16n8k8.row.col.f32.tf32.tf32.f32 "
        "{%0,%1,%2,%3},{%4,%5,%6,%7},{%8,%9},{%0,%1,%2,%3};\n"
        : "+f"(c[0]), "+f"(c[1]), "+f"(c[2]), "+f"(c[3])
        : "r"(a[0]), "r"(a[1]), "r"(a[2]), "r"(a[3]), "r"(b[0]), "r"(b[1]));
}

// -------------- TF32 GEMM: C[M,N] = A[M,K] @ B[K,N], row-major ----------------
// 128x128 block, BK=16, 8 warps (2x4), warp tile 64x32. Requires M%128==0,
// N%128==0, K%16==0 (true for all call sites).
#define TPITCH 136
__global__ __launch_bounds__(256, 2) void tgemm_k(const float* __restrict__ A,
                                                  const float* __restrict__ Bm,
                                                  float* __restrict__ C,
                                                  int Mn, int Nn, int Kn) {
    __shared__ unsigned As[16 * TPITCH];  // [k][m]
    __shared__ unsigned Bs[16 * TPITCH];  // [k][n]
    int tid = threadIdx.x;
    int row0 = blockIdx.y * 128;
    int col0 = blockIdx.x * 128;
    int w = tid >> 5, lane = tid & 31;
    int wm = (w & 1) * 64, wn = (w >> 1) * 32;
    int qr = lane >> 2, qc = lane & 3;

    float acc[4][4][4];
#pragma unroll
    for (int i = 0; i < 4; i++)
#pragma unroll
        for (int j = 0; j < 4; j++)
#pragma unroll
            for (int u = 0; u < 4; u++) acc[i][j][u] = 0.f;

    int ar = tid >> 1;              // A row within tile
    int ac = (tid & 1) * 8;         // first of 8 cols
    for (int k0 = 0; k0 < Kn; k0 += 16) {
        // load A tile (128x16) transposed into As[k][m]
        const float* Ap = &A[(size_t)(row0 + ar) * Kn + k0 + ac];
        float4 a0 = *reinterpret_cast<const float4*>(Ap);
        float4 a1 = *reinterpret_cast<const float4*>(Ap + 4);
        As[(ac + 0) * TPITCH + ar] = tf32b(a0.x);
        As[(ac + 1) * TPITCH + ar] = tf32b(a0.y);
        As[(ac + 2) * TPITCH + ar] = tf32b(a0.z);
        As[(ac + 3) * TPITCH + ar] = tf32b(a0.w);
        As[(ac + 4) * TPITCH + ar] = tf32b(a1.x);
        As[(ac + 5) * TPITCH + ar] = tf32b(a1.y);
        As[(ac + 6) * TPITCH + ar] = tf32b(a1.z);
        As[(ac + 7) * TPITCH + ar] = tf32b(a1.w);
        // load B tile (16x128) direct into Bs[k][n]
#pragma unroll
        for (int it = 0; it < 2; it++) {
            int idx = tid + it * 256;
            int kr = idx >> 5;
            int c4 = (idx & 31) * 4;
            float4 bv = *reinterpret_cast<const float4*>(&Bm[(size_t)(k0 + kr) * Nn + col0 + c4]);
            uint4 ub = make_uint4(tf32b(bv.x), tf32b(bv.y), tf32b(bv.z), tf32b(bv.w));
            *reinterpret_cast<uint4*>(&Bs[kr * TPITCH + c4]) = ub;
        }
        __syncthreads();
#pragma unroll
        for (int ks = 0; ks < 2; ks++) {
            unsigned af[4][4], bf[4][2];
#pragma unroll
            for (int mi = 0; mi < 4; mi++) {
                int m = wm + mi * 16 + qr;
                af[mi][0] = As[(ks * 8 + qc) * TPITCH + m];
                af[mi][1] = As[(ks * 8 + qc) * TPITCH + m + 8];
                af[mi][2] = As[(ks * 8 + qc + 4) * TPITCH + m];
                af[mi][3] = As[(ks * 8 + qc + 4) * TPITCH + m + 8];
            }
#pragma unroll
            for (int ni = 0; ni < 4; ni++) {
                int n = wn + ni * 8 + qr;
                bf[ni][0] = Bs[(ks * 8 + qc) * TPITCH + n];
                bf[ni][1] = Bs[(ks * 8 + qc + 4) * TPITCH + n];
            }
#pragma unroll
            for (int mi = 0; mi < 4; mi++)
#pragma unroll
                for (int ni = 0; ni < 4; ni++) mma_tf32(acc[mi][ni], af[mi], bf[ni]);
        }
        __syncthreads();
    }
#pragma unroll
    for (int mi = 0; mi < 4; mi++) {
        int r = row0 + wm + mi * 16 + qr;
#pragma unroll
        for (int ni = 0; ni < 4; ni++) {
            int c = col0 + wn + ni * 8 + 2 * qc;
            float2 v01 = make_float2(acc[mi][ni][0], acc[mi][ni][1]);
            float2 v23 = make_float2(acc[mi][ni][2], acc[mi][ni][3]);
            *reinterpret_cast<float2*>(&C[(size_t)r * Nn + c]) = v01;
            *reinterpret_cast<float2*>(&C[(size_t)(r + 8) * Nn + c]) = v23;
        }
    }
}

// ----------------------- head gate logits: x @ W_hgate -----------------------
// warp per output element (r, h)
__global__ __launch_bounds__(256) void hgate_k(const float* __restrict__ x,
                                               const float* __restrict__ W) {
    int gw = (blockIdx.x * blockDim.x + threadIdx.x) >> 5;
    int lane = threadIdx.x & 31;
    int r = gw >> 4, h = gw & 15;
    const float* xr = x + (size_t)r * DIMM;
    float s = 0.f;
#pragma unroll 8
    for (int d = lane; d < DIMM; d += 32) s += xr[d] * W[d * NH + h];
#pragma unroll
    for (int o = 16; o; o >>= 1) s += __shfl_xor_sync(0xffffffffu, s, o);
    if (lane == 0) g_hgate[r * NH + h] = s;
}

// ------------- l2norm + per-dim scale + RoPE for q,k; transpose v -------------
__global__ __launch_bounds__(256) void normrope_k(const float* __restrict__ freqs,
                                                  const float* __restrict__ q_scale,
                                                  const float* __restrict__ k_scale) {
    int gw = (blockIdx.x * blockDim.x + threadIdx.x) >> 5;
    int lane = threadIdx.x & 31;
    int row = gw / NH, h = gw - row * NH;
    int b = row / SEQ, n = row - b * SEQ;
    int d0 = lane * 2;
    size_t src = (size_t)row * DIMM + h * DHD + d0;
    float f = freqs[n * DHD + d0];
    float sf, cf;
    sincosf(f, &sf, &cf);
    {   // q
        float x0 = g_qraw[src], x1 = g_qraw[src + 1];
        float ss = x0 * x0 + x1 * x1;
#pragma unroll
        for (int o = 16; o; o >>= 1) ss += __shfl_xor_sync(0xffffffffu, ss, o);
        float inv = 1.f / fmaxf(sqrtf(ss), 1e-12f);
        x0 = x0 * inv * q_scale[h * DHD + d0];
        x1 = x1 * inv * q_scale[h * DHD + d0 + 1];
        size_t dst = ((size_t)(b * NH + h) * SEQ + n) * DHD + d0;
        g_q[dst] = x0 * cf - x1 * sf;
        g_q[dst + 1] = x1 * cf + x0 * sf;
    }
    {   // k
        float x0 = g_kraw[src], x1 = g_kraw[src + 1];
        float ss = x0 * x0 + x1 * x1;
#pragma unroll
        for (int o = 16; o; o >>= 1) ss += __shfl_xor_sync(0xffffffffu, ss, o);
        float inv = 1.f / fmaxf(sqrtf(ss), 1e-12f);
        x0 = x0 * inv * k_scale[h * DHD + d0];
        x1 = x1 * inv * k_scale[h * DHD + d0 + 1];
        size_t dst = ((size_t)(b * NH + h) * JTOT + NMEM + n) * DHD + d0;
        g_k[dst] = x0 * cf - x1 * sf;
        g_k[dst + 1] = x1 * cf + x0 * sf;
    }
    {   // v transpose copy
        size_t dst = ((size_t)(b * NH + h) * JTOT + NMEM + n) * DHD + d0;
        g_v[dst] = g_vraw[src];
        g_v[dst + 1] = g_vraw[src + 1];
    }
}

// ------------- memory kv slots: l2norm(mem_k)*k_scale, copy mem_v -------------
__global__ __launch_bounds__(256) void memprep_k(const float* __restrict__ mem_k,
                                                 const float* __restrict__ mem_v,
                                                 const float* __restrict__ k_scale) {
    int gw = (blockIdx.x * blockDim.x + threadIdx.x) >> 5;
    int lane = threadIdx.x & 31;
    int h = gw / NMEM, m = gw - h * NMEM;
    int d0 = lane * 2;
    float x0 = mem_k[(h * NMEM + m) * DHD + d0];
    float x1 = mem_k[(h * NMEM + m) * DHD + d0 + 1];
    float ss = x0 * x0 + x1 * x1;
#pragma unroll
    for (int o = 16; o; o >>= 1) ss += __shfl_xor_sync(0xffffffffu, ss, o);
    float inv = 1.f / fmaxf(sqrtf(ss), 1e-12f);
    x0 = x0 * inv * k_scale[h * DHD + d0];
    x1 = x1 * inv * k_scale[h * DHD + d0 + 1];
    float v0 = mem_v[(h * NMEM + m) * DHD + d0];
    float v1 = mem_v[(h * NMEM + m) * DHD + d0 + 1];
    for (int b = 0; b < BB; b++) {
        size_t dst = ((size_t)(b * NH + h) * JTOT + m) * DHD + d0;
        g_k[dst] = x0;
        g_k[dst + 1] = x1;
        g_v[dst] = v0;
        g_v[dst + 1] = v1;
    }
}

// ---------------- dots[b,h,i,j] = QKSCALE * q[b,h,i,:].k[b,h,j,:] -------------
__global__ __launch_bounds__(256) void dots_k() {
    int i0 = blockIdx.y * 64;
    int j0 = blockIdx.x * 64;
    if (j0 > i0 + 63 + NMEM) return;  // fully-masked tile: never read downstream
    __shared__ float Qs[64][68];
    __shared__ float Ks[64][68];
    int bh = blockIdx.z;
    const float* Q = g_q + (size_t)bh * SEQ * DHD;
    const float* K = g_k + (size_t)bh * JTOT * DHD;
    int tid = threadIdx.x;
#pragma unroll
    for (int r = 0; r < 4; r++) {
        int l = tid + r * 256;
        int i = l >> 4;
        int d4 = (l & 15) * 4;
        float4 qv = *reinterpret_cast<const float4*>(&Q[(size_t)(i0 + i) * DHD + d4]);
        *reinterpret_cast<float4*>(&Qs[i][d4]) = qv;
    }
#pragma unroll
    for (int r = 0; r < 4; r++) {
        int l = tid + r * 256;
        int j = l >> 4;
        int d4 = (l & 15) * 4;
        int jj = j0 + j;
        float4 kv = make_float4(0.f, 0.f, 0.f, 0.f);
        if (jj < JTOT) kv = *reinterpret_cast<const float4*>(&K[(size_t)jj * DHD + d4]);
        Ks[d4 + 0][j] = kv.x;
        Ks[d4 + 1][j] = kv.y;
        Ks[d4 + 2][j] = kv.z;
        Ks[d4 + 3][j] = kv.w;
    }
    __syncthreads();
    int ty = tid >> 4, tx = tid & 15;
    float acc[4][4] = {};
#pragma unroll
    for (int d = 0; d < 64; d++) {
        float a[4];
#pragma unroll
        for (int ii = 0; ii < 4; ii++) a[ii] = Qs[ty * 4 + ii][d];
        float4 bv = *reinterpret_cast<const float4*>(&Ks[d][tx * 4]);
        float bb[4] = {bv.x, bv.y, bv.z, bv.w};
#pragma unroll
        for (int ii = 0; ii < 4; ii++)
#pragma unroll
            for (int jj = 0; jj < 4; jj++) acc[ii][jj] += a[ii] * bb[jj];
    }
    float* D = g_dots + (size_t)bh * SEQ * JTOT;
#pragma unroll
    for (int ii = 0; ii < 4; ii++) {
        int i = i0 + ty * 4 + ii;
#pragma unroll
        for (int jj = 0; jj < 4; jj++) {
            int j = j0 + tx * 4 + jj;
            if (j < JTOT) D[(size_t)i * JTOT + j] = acc[ii][jj] * QKSCALE;
        }
    }
}

// ------- pre-mix + causal mask + softmax + post-mix, single smem buffer -------
__global__ __launch_bounds__(256) void mixsoft_k(const float* __restrict__ W_pre,
                                                 const float* __restrict__ W_post) {
    extern __shared__ float S[];  // NH * JTOT
    __shared__ float wpre[NH * NH], wpost[NH * NH], inv_l[NH];
    int i = blockIdx.x, b = blockIdx.y;
    int tid = threadIdx.x;
    wpre[tid] = W_pre[tid];
    wpost[tid] = W_post[tid];
    int jcnt = i + NMEM + 1;  // valid (unmasked) columns
    size_t base = ((size_t)(b * NH) * SEQ + i) * JTOT;
    for (int h = 0; h < NH; h++) {
        size_t off = base + (size_t)h * SEQ * JTOT;
        for (int j = tid; j < jcnt; j += 256) S[h * JTOT + j] = g_dots[off + j];
    }
    __syncthreads();
    // pre-softmax talking-heads mix, in place per column
    for (int j = tid; j < jcnt; j += 256) {
        float sv[NH];
#pragma unroll
        for (int h = 0; h < NH; h++) sv[h] = S[h * JTOT + j];
#pragma unroll
        for (int g = 0; g < NH; g++) {
            float a = 0.f;
#pragma unroll
            for (int h = 0; h < NH; h++) a += wpre[g * NH + h] * sv[h];
            S[g * JTOT + j] = a;
        }
    }
    __syncthreads();
    int w = tid >> 5, lane = tid & 31;
    for (int g = w; g < NH; g += 8) {
        float mx = -3.0e38f;
        for (int j = lane; j < jcnt; j += 32) mx = fmaxf(mx, S[g * JTOT + j]);
#pragma unroll
        for (int o = 16; o; o >>= 1) mx = fmaxf(mx, __shfl_xor_sync(0xffffffffu, mx, o));
        float sum = 0.f;
        for (int j = lane; j < jcnt; j += 32) {
            float e = __expf(S[g * JTOT + j] - mx);
            S[g * JTOT + j] = e;
            sum += e;
        }
#pragma unroll
        for (int o = 16; o; o >>= 1) sum += __shfl_xor_sync(0xffffffffu, sum, o);
        if (lane == 0) inv_l[g] = 1.f / sum;
    }
    __syncthreads();
    // post-softmax mix, write back to g_dots; masked region is exact zero
    for (int j = tid; j < jcnt; j += 256) {
        float pv[NH];
#pragma unroll
        for (int h = 0; h < NH; h++) pv[h] = S[h * JTOT + j] * inv_l[h];
#pragma unroll
        for (int g = 0; g < NH; g++) {
            float a = 0.f;
#pragma unroll
            for (int h = 0; h < NH; h++) a += wpost[g * NH + h] * pv[h];
            g_dots[base + (size_t)g * SEQ * JTOT + j] = a;
        }
    }
    for (int j = jcnt + tid; j < JTOT; j += 256) {
#pragma unroll
        for (int g = 0; g < NH; g++) g_dots[base + (size_t)g * SEQ * JTOT + j] = 0.f;
    }
}

// ------------ out[b,g,i,d] = sum_j attn * v, fused head/value gates -----------
__global__ __launch_bounds__(256) void outgemm_k(const float* __restrict__ b_h,
                                                 const float* __restrict__ b_v,
                                                 float* __restrict__ outg) {
    __shared__ float As[16][68];
    __shared__ float Vs[16][68];
    int bg = blockIdx.y;
    int b = bg >> 4, g = bg & 15;
    int i0 = blockIdx.x * 64;
    const float* Arow = g_dots + (size_t)bg * SEQ * JTOT;
    const float* V = g_v + (size_t)bg * JTOT * DHD;
    int tid = threadIdx.x;
    int ty = tid >> 4, tx = tid & 15;
    float acc[4][4] = {};
    int kmax = i0 + 80;  // attn is exact zero beyond i+NMEM; i0+80 covers tile
    if (kmax > JTOT) kmax = JTOT;
    for (int k0 = 0; k0 < kmax; k0 += 16) {
        {
            int i = tid >> 2;
            int c4 = (tid & 3) * 4;
            float4 av = *reinterpret_cast<const float4*>(&Arow[(size_t)(i0 + i) * JTOT + k0 + c4]);
            As[c4 + 0][i] = av.x;
            As[c4 + 1][i] = av.y;
            As[c4 + 2][i] = av.z;
            As[c4 + 3][i] = av.w;
        }
        {
            int kk = tid >> 4;
            int d4 = (tid & 15) * 4;
            *reinterpret_cast<float4*>(&Vs[kk][d4]) =
                *reinterpret_cast<const float4*>(&V[(size_t)(k0 + kk) * DHD + d4]);
        }
        __syncthreads();
#pragma unroll
        for (int kk = 0; kk < 16; kk++) {
            float a[4];
#pragma unroll
            for (int ii = 0; ii < 4; ii++) a[ii] = As[kk][ty * 4 + ii];
            float4 vv = *reinterpret_cast<const float4*>(&Vs[kk][tx * 4]);
            float vb[4] = {vv.x, vv.y, vv.z, vv.w};
#pragma unroll
            for (int ii = 0; ii < 4; ii++)
#pragma unroll
                for (int jj = 0; jj < 4; jj++) acc[ii][jj] += a[ii] * vb[jj];
        }
        __syncthreads();
    }
#pragma unroll
    for (int ii = 0; ii < 4; ii++) {
        int i = i0 + ty * 4 + ii;
        int r = b * SEQ + i;
        float hg = 1.f / (1.f + __expf(-(g_hgate[r * NH + g] + b_h[g])));
#pragma unroll
        for (int jj = 0; jj < 4; jj++) {
            int d = tx * 4 + jj;
            int c = g * DHD + d;
            float vg = 1.f / (1.f + __expf(-(g_vgate[(size_t)r * DIMM + c] + b_v[c])));
            outg[(size_t)r * DIMM + c] = acc[ii][jj] * hg * vg;
        }
    }
}

// ------------------------------------------------------------------------------
extern "C" void kernel_launch(void* const* d_in, const int* in_sizes, int n_in,
                              void* d_out, int out_size) {
    const float* x       = (const float*)d_in[0];
    const float* freqs   = (const float*)d_in[1];
    const float* Wq      = (const float*)d_in[2];
    const float* Wk      = (const float*)d_in[3];
    const float* Wv      = (const float*)d_in[4];
    const float* q_scale = (const float*)d_in[5];
    const float* k_scale = (const float*)d_in[6];
    const float* mem_k   = (const float*)d_in[7];
    const float* mem_v   = (const float*)d_in[8];
    const float* W_pre   = (const float*)d_in[9];
    const float* W_post  = (const float*)d_in[10];
    const float* W_hgate = (const float*)d_in[11];
    const float* b_hgate = (const float*)d_in[12];
    const float* W_vgate = (const float*)d_in[13];
    const float* b_vgate = (const float*)d_in[14];
    const float* Wo      = (const float*)d_in[15];
    float* out = (float*)d_out;

    float *qraw, *kraw, *vraw, *vgate, *outg;
    cudaGetSymbolAddress((void**)&qraw, g_qraw);
    cudaGetSymbolAddress((void**)&kraw, g_kraw);
    cudaGetSymbolAddress((void**)&vraw, g_vraw);
    cudaGetSymbolAddress((void**)&vgate, g_vgate);
    cudaGetSymbolAddress((void**)&outg, g_outg);

    dim3 gBig(DIMM / 128, ROWS / 128);  // (8, 32)

    // 1) projections + gate logits (tf32 tensor cores)
    tgemm_k<<<gBig, 256>>>(x, Wq, qraw, ROWS, DIMM, DIMM);
    tgemm_k<<<gBig, 256>>>(x, Wk, kraw, ROWS, DIMM, DIMM);
    tgemm_k<<<gBig, 256>>>(x, Wv, vraw, ROWS, DIMM, DIMM);
    tgemm_k<<<gBig, 256>>>(x, W_vgate, vgate, ROWS, DIMM, DIMM);
    hgate_k<<<(ROWS * NH) / 8, 256>>>(x, W_hgate);

    // 2) l2norm + scale + rope + head-major layout; memory kv slots
    normrope_k<<<(ROWS * NH) / 8, 256>>>(freqs, q_scale, k_scale);
    memprep_k<<<(NH * NMEM) / 8, 256>>>(mem_k, mem_v, k_scale);

    // 3) attention scores (causal tiles only)
    dots_k<<<dim3((JTOT + 63) / 64, SEQ / 64, BB * NH), 256>>>();

    // 4) talking-heads mix + causal softmax + post-mix (in place, 1 smem buffer)
    int smem = NH * JTOT * (int)sizeof(float);  // 66,560 B
    cudaFuncSetAttribute(mixsoft_k, cudaFuncAttributeMaxDynamicSharedMemorySize, smem);
    mixsoft_k<<<dim3(SEQ, BB), 256, smem>>>(W_pre, W_post);

    // 5) attn @ v + head gate + value gate (k-loop capped by causality)
    outgemm_k<<<dim3(SEQ / 64, BB * NH), 256>>>(b_hgate, b_vgate, outg);

    // 6) output projection (tf32)
    tgemm_k<<<gBig, 256>>>(outg, Wo, out, ROWS, DIMM, DIMM);
}

// round 3
// speedup vs baseline: 2.4742x; 1.2128x over previous
#include <cuda_runtime.h>
#include <math.h>

#define BB 4
#define SEQ 1024
#define DIMM 1024
#define NH 16
#define DHD 64
#define NMEM 16
#define JTOT (SEQ + NMEM)   /* 1040 */
#define ROWS (BB * SEQ)     /* 4096 */
#define QKSCALE 10.0f

// ------------------------- device scratch (no allocs) -------------------------
__device__ float g_qraw[ROWS * DIMM];
__device__ float g_kraw[ROWS * DIMM];
__device__ float g_vraw[ROWS * DIMM];
__device__ float g_vgate[ROWS * DIMM];
__device__ float g_hgate[ROWS * NH];
__device__ float g_q[(size_t)BB * NH * SEQ * DHD];
__device__ float g_k[(size_t)BB * NH * JTOT * DHD];
__device__ float g_v[(size_t)BB * NH * JTOT * DHD];
__device__ float g_dots[(size_t)BB * NH * SEQ * JTOT];
__device__ float g_outg[ROWS * DIMM];

// ------------------------------ tf32 helpers ---------------------------------
__device__ __forceinline__ unsigned tf32b(float x) {
    unsigned u;
    asm("cvt.rna.tf32.f32 %0, %1;" : "=r"(u) : "f"(x));
    return u;
}
__device__ __forceinline__ void tf32pair(float x, unsigned& hi, unsigned& lo) {
    hi = tf32b(x);
    lo = tf32b(x - __uint_as_float(hi));
}
__device__ __forceinline__ void mma_tf32(float c[4], const unsigned a[4], const unsigned b[2]) {
    asm volatile(
        "mma.sync.aligned.m16n8k8.row.col.f32.tf32.tf32.f32 "
        "{%0,%1,%2,%3},{%4,%5,%6,%7},{%8,%9},{%0,%1,%2,%3};\n"
        : "+f"(c[0]), "+f"(c[1]), "+f"(c[2]), "+f"(c[3])
        : "r"(a[0]), "r"(a[1]), "r"(a[2]), "r"(a[3]), "r"(b[0]), "r"(b[1]));
}
__device__ __forceinline__ void cp16(void* smem, const void* gmem) {
    unsigned s = (unsigned)__cvta_generic_to_shared(smem);
    asm volatile("cp.async.cg.shared.global [%0], [%1], 16;\n" ::"r"(s), "l"(gmem));
}
#define CP_COMMIT asm volatile("cp.async.commit_group;\n")
#define CP_WAIT(n) asm volatile("cp.async.wait_group %0;\n" ::"n"(n))

__device__ __forceinline__ float sigm(float x) { return 1.f / (1.f + __expf(-x)); }

// -------------- TF32 GEMM: C[M,N] = A[M,K] @ B[K,N], cp.async 2-stage ---------
#define APITCH 20   /* floats: 20*qr mod 32 spans all banks */
#define BPITCH 136  /* floats: 136 mod 32 == 8 -> conflict-free b-frag loads */
__global__ __launch_bounds__(256, 2) void tgemm_k(const float* __restrict__ A,
                                                  const float* __restrict__ Bm,
                                                  float* __restrict__ C,
                                                  int Mn, int Nn, int Kn) {
    __shared__ float As[2][128 * APITCH];
    __shared__ float Bs[2][16 * BPITCH];
    int tid = threadIdx.x;
    int row0 = blockIdx.y * 128, col0 = blockIdx.x * 128;
    int w = tid >> 5, lane = tid & 31;
    int wm = (w & 1) * 64, wn = (w >> 1) * 32;
    int qr = lane >> 2, qc = lane & 3;

    float acc[4][4][4];
#pragma unroll
    for (int i = 0; i < 4; i++)
#pragma unroll
        for (int j = 0; j < 4; j++)
#pragma unroll
            for (int u = 0; u < 4; u++) acc[i][j][u] = 0.f;

    int KT = Kn >> 4;
    // prefetch stage 0
    {
#pragma unroll
        for (int it = 0; it < 2; it++) {
            int c = tid + it * 256;
            int ar = c >> 2, ac = (c & 3) * 4;
            cp16(&As[0][ar * APITCH + ac], &A[(size_t)(row0 + ar) * Kn + ac]);
            int br = c >> 5, bc = (c & 31) * 4;
            cp16(&Bs[0][br * BPITCH + bc], &Bm[(size_t)br * Nn + col0 + bc]);
        }
        CP_COMMIT;
    }
    for (int kt = 0; kt < KT; kt++) {
        if (kt + 1 < KT) {
            int k0 = (kt + 1) << 4;
            int st = (kt + 1) & 1;
#pragma unroll
            for (int it = 0; it < 2; it++) {
                int c = tid + it * 256;
                int ar = c >> 2, ac = (c & 3) * 4;
                cp16(&As[st][ar * APITCH + ac], &A[(size_t)(row0 + ar) * Kn + k0 + ac]);
                int br = c >> 5, bc = (c & 31) * 4;
                cp16(&Bs[st][br * BPITCH + bc], &Bm[(size_t)(k0 + br) * Nn + col0 + bc]);
            }
            CP_COMMIT;
            CP_WAIT(1);
        } else {
            CP_WAIT(0);
        }
        __syncthreads();
        const float* as = As[kt & 1];
        const float* bs = Bs[kt & 1];
#pragma unroll
        for (int ks = 0; ks < 2; ks++) {
            int k = ks * 8 + qc;
            unsigned af[4][4], bf[4][2];
#pragma unroll
            for (int mi = 0; mi < 4; mi++) {
                int m = wm + mi * 16 + qr;
                af[mi][0] = tf32b(as[m * APITCH + k]);
                af[mi][1] = tf32b(as[(m + 8) * APITCH + k]);
                af[mi][2] = tf32b(as[m * APITCH + k + 4]);
                af[mi][3] = tf32b(as[(m + 8) * APITCH + k + 4]);
            }
#pragma unroll
            for (int ni = 0; ni < 4; ni++) {
                int n = wn + ni * 8 + qr;
                bf[ni][0] = tf32b(bs[k * BPITCH + n]);
                bf[ni][1] = tf32b(bs[(k + 4) * BPITCH + n]);
            }
#pragma unroll
            for (int mi = 0; mi < 4; mi++)
#pragma unroll
                for (int ni = 0; ni < 4; ni++) mma_tf32(acc[mi][ni], af[mi], bf[ni]);
        }
        __syncthreads();
    }
#pragma unroll
    for (int mi = 0; mi < 4; mi++) {
        int r = row0 + wm + mi * 16 + qr;
#pragma unroll
        for (int ni = 0; ni < 4; ni++) {
            int c = col0 + wn + ni * 8 + 2 * qc;
            *reinterpret_cast<float2*>(&C[(size_t)r * Nn + c]) =
                make_float2(acc[mi][ni][0], acc[mi][ni][1]);
            *reinterpret_cast<float2*>(&C[(size_t)(r + 8) * Nn + c]) =
                make_float2(acc[mi][ni][2], acc[mi][ni][3]);
        }
    }
}

// ----------------- head gate logits: warp per row, 16 accums ------------------
__global__ __launch_bounds__(256) void hgate_k(const float* __restrict__ x,
                                               const float* __restrict__ W) {
    int r = (blockIdx.x * blockDim.x + threadIdx.x) >> 5;
    int lane = threadIdx.x & 31;
    const float* xr = x + (size_t)r * DIMM;
    float a[16];
#pragma unroll
    for (int h = 0; h < 16; h++) a[h] = 0.f;
    for (int d = lane; d < DIMM; d += 32) {
        float xv = xr[d];
        const float4* wr = reinterpret_cast<const float4*>(W + d * NH);
        float4 w0 = wr[0], w1 = wr[1], w2 = wr[2], w3 = wr[3];
        a[0] += xv * w0.x; a[1] += xv * w0.y; a[2] += xv * w0.z; a[3] += xv * w0.w;
        a[4] += xv * w1.x; a[5] += xv * w1.y; a[6] += xv * w1.z; a[7] += xv * w1.w;
        a[8] += xv * w2.x; a[9] += xv * w2.y; a[10] += xv * w2.z; a[11] += xv * w2.w;
        a[12] += xv * w3.x; a[13] += xv * w3.y; a[14] += xv * w3.z; a[15] += xv * w3.w;
    }
#pragma unroll
    for (int h = 0; h < 16; h++)
#pragma unroll
        for (int o = 16; o; o >>= 1) a[h] += __shfl_xor_sync(0xffffffffu, a[h], o);
    if (lane == 0) {
        float4* dst = reinterpret_cast<float4*>(&g_hgate[r * NH]);
        dst[0] = make_float4(a[0], a[1], a[2], a[3]);
        dst[1] = make_float4(a[4], a[5], a[6], a[7]);
        dst[2] = make_float4(a[8], a[9], a[10], a[11]);
        dst[3] = make_float4(a[12], a[13], a[14], a[15]);
    }
}

// ------------- l2norm + per-dim scale + RoPE for q,k; transpose v -------------
__global__ __launch_bounds__(256) void normrope_k(const float* __restrict__ freqs,
                                                  const float* __restrict__ q_scale,
                                                  const float* __restrict__ k_scale) {
    int gw = (blockIdx.x * blockDim.x + threadIdx.x) >> 5;
    int lane = threadIdx.x & 31;
    int row = gw / NH, h = gw - row * NH;
    int b = row / SEQ, n = row - b * SEQ;
    int d0 = lane * 2;
    size_t src = (size_t)row * DIMM + h * DHD + d0;
    float f = freqs[n * DHD + d0];
    float sf, cf;
    sincosf(f, &sf, &cf);
    {   // q
        float x0 = g_qraw[src], x1 = g_qraw[src + 1];
        float ss = x0 * x0 + x1 * x1;
#pragma unroll
        for (int o = 16; o; o >>= 1) ss += __shfl_xor_sync(0xffffffffu, ss, o);
        float inv = 1.f / fmaxf(sqrtf(ss), 1e-12f);
        x0 = x0 * inv * q_scale[h * DHD + d0];
        x1 = x1 * inv * q_scale[h * DHD + d0 + 1];
        size_t dst = ((size_t)(b * NH + h) * SEQ + n) * DHD + d0;
        g_q[dst] = x0 * cf - x1 * sf;
        g_q[dst + 1] = x1 * cf + x0 * sf;
    }
    {   // k
        float x0 = g_kraw[src], x1 = g_kraw[src + 1];
        float ss = x0 * x0 + x1 * x1;
#pragma unroll
        for (int o = 16; o; o >>= 1) ss += __shfl_xor_sync(0xffffffffu, ss, o);
        float inv = 1.f / fmaxf(sqrtf(ss), 1e-12f);
        x0 = x0 * inv * k_scale[h * DHD + d0];
        x1 = x1 * inv * k_scale[h * DHD + d0 + 1];
        size_t dst = ((size_t)(b * NH + h) * JTOT + NMEM + n) * DHD + d0;
        g_k[dst] = x0 * cf - x1 * sf;
        g_k[dst + 1] = x1 * cf + x0 * sf;
    }
    {   // v transpose copy
        size_t dst = ((size_t)(b * NH + h) * JTOT + NMEM + n) * DHD + d0;
        g_v[dst] = g_vraw[src];
        g_v[dst + 1] = g_vraw[src + 1];
    }
}

// ------------- memory kv slots: l2norm(mem_k)*k_scale, copy mem_v -------------
__global__ __launch_bounds__(256) void memprep_k(const float* __restrict__ mem_k,
                                                 const float* __restrict__ mem_v,
                                                 const float* __restrict__ k_scale) {
    int gw = (blockIdx.x * blockDim.x + threadIdx.x) >> 5;
    int lane = threadIdx.x & 31;
    int h = gw / NMEM, m = gw - h * NMEM;
    int d0 = lane * 2;
    float x0 = mem_k[(h * NMEM + m) * DHD + d0];
    float x1 = mem_k[(h * NMEM + m) * DHD + d0 + 1];
    float ss = x0 * x0 + x1 * x1;
#pragma unroll
    for (int o = 16; o; o >>= 1) ss += __shfl_xor_sync(0xffffffffu, ss, o);
    float inv = 1.f / fmaxf(sqrtf(ss), 1e-12f);
    x0 = x0 * inv * k_scale[h * DHD + d0];
    x1 = x1 * inv * k_scale[h * DHD + d0 + 1];
    float v0 = mem_v[(h * NMEM + m) * DHD + d0];
    float v1 = mem_v[(h * NMEM + m) * DHD + d0 + 1];
    for (int b = 0; b < BB; b++) {
        size_t dst = ((size_t)(b * NH + h) * JTOT + m) * DHD + d0;
        g_k[dst] = x0;
        g_k[dst + 1] = x1;
        g_v[dst] = v0;
        g_v[dst + 1] = v1;
    }
}

// -------- dots[b,h,i,j] = QKSCALE * q.k  (3xTF32 tensor-core, causal) ---------
__global__ __launch_bounds__(256) void dots_k() {
    int i0 = blockIdx.y * 64;
    int j0 = blockIdx.x * 64;
    if (j0 > i0 + 63 + NMEM) return;
    __shared__ float Qs[64 * 68];  // [i][d]
    __shared__ float Ks[64 * 68];  // [j][d] (B col-major via row.col mma)
    int bh = blockIdx.z;
    const float* Q = g_q + (size_t)bh * SEQ * DHD;
    const float* K = g_k + (size_t)bh * JTOT * DHD;
    int tid = threadIdx.x;
#pragma unroll
    for (int it = 0; it < 4; it++) {
        int c = tid + it * 256;
        int r = c >> 4, d4 = (c & 15) * 4;
        *reinterpret_cast<float4*>(&Qs[r * 68 + d4]) =
            *reinterpret_cast<const float4*>(&Q[(size_t)(i0 + r) * DHD + d4]);
        int jj = j0 + r;
        float4 kv = make_float4(0.f, 0.f, 0.f, 0.f);
        if (jj < JTOT) kv = *reinterpret_cast<const float4*>(&K[(size_t)jj * DHD + d4]);
        *reinterpret_cast<float4*>(&Ks[r * 68 + d4]) = kv;
    }
    __syncthreads();
    int w = tid >> 5, lane = tid & 31;
    int wm = (w >> 1) * 16, wn = (w & 1) * 32;
    int qr = lane >> 2, qc = lane & 3;
    float acc[4][4] = {};
#pragma unroll
    for (int kk = 0; kk < 8; kk++) {
        int k = kk * 8 + qc;
        unsigned ah[4], al[4];
        tf32pair(Qs[(wm + qr) * 68 + k], ah[0], al[0]);
        tf32pair(Qs[(wm + qr + 8) * 68 + k], ah[1], al[1]);
        tf32pair(Qs[(wm + qr) * 68 + k + 4], ah[2], al[2]);
        tf32pair(Qs[(wm + qr + 8) * 68 + k + 4], ah[3], al[3]);
#pragma unroll
        for (int ni = 0; ni < 4; ni++) {
            int n = wn + ni * 8 + qr;
            unsigned bh2[2], bl2[2];
            tf32pair(Ks[n * 68 + k], bh2[0], bl2[0]);
            tf32pair(Ks[n * 68 + k + 4], bh2[1], bl2[1]);
            mma_tf32(acc[ni], ah, bh2);
            mma_tf32(acc[ni], ah, bl2);
            mma_tf32(acc[ni], al, bh2);
        }
    }
    float* D = g_dots + (size_t)bh * SEQ * JTOT;
#pragma unroll
    for (int ni = 0; ni < 4; ni++) {
        int i = i0 + wm + qr;
        int j = j0 + wn + ni * 8 + 2 * qc;
        if (j < JTOT) {
            *reinterpret_cast<float2*>(&D[(size_t)i * JTOT + j]) =
                make_float2(acc[ni][0] * QKSCALE, acc[ni][1] * QKSCALE);
            *reinterpret_cast<float2*>(&D[(size_t)(i + 8) * JTOT + j]) =
                make_float2(acc[ni][2] * QKSCALE, acc[ni][3] * QKSCALE);
        }
    }
}

// ------- pre-mix + causal mask + softmax + post-mix, band-limited zeros -------
__global__ __launch_bounds__(256) void mixsoft_k(const float* __restrict__ W_pre,
                                                 const float* __restrict__ W_post) {
    extern __shared__ float S[];  // NH * JTOT
    __shared__ float wpre[NH * NH], wpost[NH * NH], inv_l[NH];
    int i = blockIdx.x, b = blockIdx.y;
    int tid = threadIdx.x;
    wpre[tid] = W_pre[tid];
    wpost[tid] = W_post[tid];
    int jcnt = i + NMEM + 1;
    size_t base = ((size_t)(b * NH) * SEQ + i) * JTOT;
    for (int h = 0; h < NH; h++) {
        size_t off = base + (size_t)h * SEQ * JTOT;
        for (int j = tid; j < jcnt; j += 256) S[h * JTOT + j] = g_dots[off + j];
    }
    __syncthreads();
    for (int j = tid; j < jcnt; j += 256) {
        float sv[NH];
#pragma unroll
        for (int h = 0; h < NH; h++) sv[h] = S[h * JTOT + j];
#pragma unroll
        for (int g = 0; g < NH; g++) {
            float a = 0.f;
#pragma unroll
            for (int h = 0; h < NH; h++) a += wpre[g * NH + h] * sv[h];
            S[g * JTOT + j] = a;
        }
    }
    __syncthreads();
    int w = tid >> 5, lane = tid & 31;
    for (int g = w; g < NH; g += 8) {
        float mx = -3.0e38f;
        for (int j = lane; j < jcnt; j += 32) mx = fmaxf(mx, S[g * JTOT + j]);
#pragma unroll
        for (int o = 16; o; o >>= 1) mx = fmaxf(mx, __shfl_xor_sync(0xffffffffu, mx, o));
        float sum = 0.f;
        for (int j = lane; j < jcnt; j += 32) {
            float e = __expf(S[g * JTOT + j] - mx);
            S[g * JTOT + j] = e;
            sum += e;
        }
#pragma unroll
        for (int o = 16; o; o >>= 1) sum += __shfl_xor_sync(0xffffffffu, sum, o);
        if (lane == 0) inv_l[g] = 1.f / sum;
    }
    __syncthreads();
    for (int j = tid; j < jcnt; j += 256) {
        float pv[NH];
#pragma unroll
        for (int h = 0; h < NH; h++) pv[h] = S[h * JTOT + j] * inv_l[h];
#pragma unroll
        for (int g = 0; g < NH; g++) {
            float a = 0.f;
#pragma unroll
            for (int h = 0; h < NH; h++) a += wpost[g * NH + h] * pv[h];
            g_dots[base + (size_t)g * SEQ * JTOT + j] = a;
        }
    }
    // zero only the band outgemm will actually read: [jcnt, (i&~63)+80)
    int zend = (i & ~63) + 80;
    if (zend > JTOT) zend = JTOT;
    for (int j = jcnt + tid; j < zend; j += 256) {
#pragma unroll
        for (int g = 0; g < NH; g++) g_dots[base + (size_t)g * SEQ * JTOT + j] = 0.f;
    }
}

// ------ out[b,g,i,d] = attn @ v (3xTF32 mma) + fused head/value gates ---------
#define OPITCH 20
#define VPITCH 17
__global__ __launch_bounds__(256) void outgemm_k(const float* __restrict__ b_h,
                                                 const float* __restrict__ b_v,
                                                 float* __restrict__ outg) {
    __shared__ float As[64 * OPITCH];  // attn chunk [i][k]
    __shared__ float Vs[64 * VPITCH];  // V^T chunk [d][k]
    int bg = blockIdx.y;
    int b = bg >> 4, g = bg & 15;
    int i0 = blockIdx.x * 64;
    const float* Arow = g_dots + (size_t)bg * SEQ * JTOT;
    const float* V = g_v + (size_t)bg * JTOT * DHD;
    int tid = threadIdx.x;
    int w = tid >> 5, lane = tid & 31;
    int wm = (w >> 1) * 16, wn = (w & 1) * 32;
    int qr = lane >> 2, qc = lane & 3;
    float acc[4][4] = {};
    int kmax = i0 + 80;
    if (kmax > JTOT) kmax = JTOT;
    for (int k0 = 0; k0 < kmax; k0 += 16) {
        {
            int r = tid >> 2, c4 = (tid & 3) * 4;
            *reinterpret_cast<float4*>(&As[r * OPITCH + c4]) =
                *reinterpret_cast<const float4*>(&Arow[(size_t)(i0 + r) * JTOT + k0 + c4]);
        }
        {
            int kk = tid >> 4, d4 = (tid & 15) * 4;
            float4 vv = *reinterpret_cast<const float4*>(&V[(size_t)(k0 + kk) * DHD + d4]);
            Vs[(d4 + 0) * VPITCH + kk] = vv.x;
            Vs[(d4 + 1) * VPITCH + kk] = vv.y;
            Vs[(d4 + 2) * VPITCH + kk] = vv.z;
            Vs[(d4 + 3) * VPITCH + kk] = vv.w;
        }
        __syncthreads();
#pragma unroll
        for (int ks = 0; ks < 2; ks++) {
            int k = ks * 8 + qc;
            unsigned ah[4], al[4];
            tf32pair(As[(wm + qr) * OPITCH + k], ah[0], al[0]);
            tf32pair(As[(wm + qr + 8) * OPITCH + k], ah[1], al[1]);
            tf32pair(As[(wm + qr) * OPITCH + k + 4], ah[2], al[2]);
            tf32pair(As[(wm + qr + 8) * OPITCH + k + 4], ah[3], al[3]);
#pragma unroll
            for (int ni = 0; ni < 4; ni++) {
                int n = wn + ni * 8 + qr;
                unsigned bh2[2], bl2[2];
                tf32pair(Vs[n * VPITCH + k], bh2[0], bl2[0]);
                tf32pair(Vs[n * VPITCH + k + 4], bh2[1], bl2[1]);
                mma_tf32(acc[ni], ah, bh2);
                mma_tf32(acc[ni], ah, bl2);
                mma_tf32(acc[ni], al, bh2);
            }
        }
        __syncthreads();
    }
#pragma unroll
    for (int rr = 0; rr < 2; rr++) {
        int i = i0 + wm + qr + rr * 8;
        int r = b * SEQ + i;
        float hg = sigm(g_hgate[r * NH + g] + b_h[g]);
#pragma unroll
        for (int ni = 0; ni < 4; ni++) {
            int c = g * DHD + wn + ni * 8 + 2 * qc;
            float2 vgl = *reinterpret_cast<const float2*>(&g_vgate[(size_t)r * DIMM + c]);
            float2 bvl = *reinterpret_cast<const float2*>(&b_v[c]);
            float o0 = acc[ni][rr * 2 + 0] * hg * sigm(vgl.x + bvl.x);
            float o1 = acc[ni][rr * 2 + 1] * hg * sigm(vgl.y + bvl.y);
            *reinterpret_cast<float2*>(&outg[(size_t)r * DIMM + c]) = make_float2(o0, o1);
        }
    }
}

// ------------------------------------------------------------------------------
extern "C" void kernel_launch(void* const* d_in, const int* in_sizes, int n_in,
                              void* d_out, int out_size) {
    const float* x       = (const float*)d_in[0];
    const float* freqs   = (const float*)d_in[1];
    const float* Wq      = (const float*)d_in[2];
    const float* Wk      = (const float*)d_in[3];
    const float* Wv      = (const float*)d_in[4];
    const float* q_scale = (const float*)d_in[5];
    const float* k_scale = (const float*)d_in[6];
    const float* mem_k   = (const float*)d_in[7];
    const float* mem_v   = (const float*)d_in[8];
    const float* W_pre   = (const float*)d_in[9];
    const float* W_post  = (const float*)d_in[10];
    const float* W_hgate = (const float*)d_in[11];
    const float* b_hgate = (const float*)d_in[12];
    const float* W_vgate = (const float*)d_in[13];
    const float* b_vgate = (const float*)d_in[14];
    const float* Wo      = (const float*)d_in[15];
    float* out = (float*)d_out;

    float *qraw, *kraw, *vraw, *vgate, *outg;
    cudaGetSymbolAddress((void**)&qraw, g_qraw);
    cudaGetSymbolAddress((void**)&kraw, g_kraw);
    cudaGetSymbolAddress((void**)&vraw, g_vraw);
    cudaGetSymbolAddress((void**)&vgate, g_vgate);
    cudaGetSymbolAddress((void**)&outg, g_outg);

    dim3 gBig(DIMM / 128, ROWS / 128);  // (8, 32)

    // 1) projections + gate logits (tf32 tensor cores, cp.async pipelined)
    tgemm_k<<<gBig, 256>>>(x, Wq, qraw, ROWS, DIMM, DIMM);
    tgemm_k<<<gBig, 256>>>(x, Wk, kraw, ROWS, DIMM, DIMM);
    tgemm_k<<<gBig, 256>>>(x, Wv, vraw, ROWS, DIMM, DIMM);
    tgemm_k<<<gBig, 256>>>(x, W_vgate, vgate, ROWS, DIMM, DIMM);
    hgate_k<<<ROWS / 8, 256>>>(x, W_hgate);

    // 2) l2norm + scale + rope + head-major layout; memory kv slots
    normrope_k<<<(ROWS * NH) / 8, 256>>>(freqs, q_scale, k_scale);
    memprep_k<<<(NH * NMEM) / 8, 256>>>(mem_k, mem_v, k_scale);

    // 3) attention scores (3xTF32 mma, causal tiles only)
    dots_k<<<dim3((JTOT + 63) / 64, SEQ / 64, BB * NH), 256>>>();

    // 4) talking-heads mix + causal softmax + post-mix
    int smem = NH * JTOT * (int)sizeof(float);  // 66,560 B
    cudaFuncSetAttribute(mixsoft_k, cudaFuncAttributeMaxDynamicSharedMemorySize, smem);
    mixsoft_k<<<dim3(SEQ, BB), 256, smem>>>(W_pre, W_post);

    // 5) attn @ v (3xTF32 mma) + gates
    outgemm_k<<<dim3(SEQ / 64, BB * NH), 256>>>(b_hgate, b_vgate, outg);

    // 6) output projection (tf32)
    tgemm_k<<<gBig, 256>>>(outg, Wo, out, ROWS, DIMM, DIMM);
}